// round 16
// baseline (speedup 1.0000x reference)
#include <cuda_runtime.h>
#include <cuda_fp16.h>
#include <stdint.h>

// Problem constants
#define VV   50257
#define VPAD 50304          // 393 * 128
#define BB   128
#define TT   1024
#define EE   256
#define HH   512
#define ROWG 16             // rows per rowgroup
#define NRG  8              // rowgroups
#define NSPL 16             // gate-split blocks per rowgroup
#define WPITCH 520          // W_hh smem pitch (halfs): 1040B, %128=16 -> conflict-free ldmatrix
#define HPITCH 520          // h buffer pitch (halfs)
#define OFF_H0 (128 * WPITCH * 2)               // 133120
#define OFF_H1 (OFF_H0 + ROWG * HPITCH * 2)     // 149760
#define SMEM_BYTES (OFF_H1 + ROWG * HPITCH * 2) // 166400 <= 232448 cap -> 1 CTA/SM

#define PPITCH 264          // proj kernel smem pitch (halfs): 528B, %128=16
#define PSMEM  (2 * 128 * PPITCH * 2)           // 135168 B -> 1 CTA/SM

// Persistent device scratch
// g_proj layout is UNIT-MAJOR: proj[v][unit*4 + gate]  (gate: 0=i,1=f,2=g,3=o)
__device__ __half   g_proj[(size_t)VPAD * 2048];  // 206 MB
__device__ __half   g_hbuf[2][BB][HH];            // double-buffered recurrent h (fp16)
__device__ float    g_lastH[BB][HH];
__device__ float    g_lastC[BB][HH];
__device__ unsigned g_ctrB[NRG][NSPL][32];        // per-producer-block counters, 128B apart

// ---------------------------------------------------------------------------
__device__ __forceinline__ uint32_t smem_u32(const void* p) {
    return (uint32_t)__cvta_generic_to_shared(p);
}
__device__ __forceinline__ void ldsm_x4(uint32_t& r0, uint32_t& r1, uint32_t& r2, uint32_t& r3, uint32_t a) {
    asm volatile("ldmatrix.sync.aligned.m8n8.x4.shared.b16 {%0,%1,%2,%3}, [%4];\n"
                 : "=r"(r0), "=r"(r1), "=r"(r2), "=r"(r3) : "r"(a));
}
__device__ __forceinline__ void ldsm_x2(uint32_t& r0, uint32_t& r1, uint32_t a) {
    asm volatile("ldmatrix.sync.aligned.m8n8.x2.shared.b16 {%0,%1}, [%2];\n"
                 : "=r"(r0), "=r"(r1) : "r"(a));
}
__device__ __forceinline__ void mma16816(float* d, uint32_t a0, uint32_t a1, uint32_t a2, uint32_t a3,
                                         uint32_t b0, uint32_t b1) {
    asm volatile("mma.sync.aligned.m16n8k16.row.col.f32.f16.f16.f32 "
                 "{%0,%1,%2,%3}, {%4,%5,%6,%7}, {%8,%9}, {%0,%1,%2,%3};\n"
                 : "+f"(d[0]), "+f"(d[1]), "+f"(d[2]), "+f"(d[3])
                 : "r"(a0), "r"(a1), "r"(a2), "r"(a3), "r"(b0), "r"(b1));
}
__device__ __forceinline__ unsigned ld_acquire(const unsigned* p) {
    unsigned v;
    asm volatile("ld.global.acquire.gpu.b32 %0, [%1];\n" : "=r"(v) : "l"(p) : "memory");
    return v;
}
__device__ __forceinline__ void red_release_add1(unsigned* p) {
    asm volatile("red.release.gpu.global.add.u32 [%0], %1;\n" :: "l"(p), "r"(1u) : "memory");
}
// MUFU.TANH-based activations: 1 MUFU each
__device__ __forceinline__ float tanha(float x) {
    float y; asm("tanh.approx.f32 %0, %1;\n" : "=f"(y) : "f"(x)); return y;
}
__device__ __forceinline__ float siga(float x) {
    return fmaf(tanha(0.5f * x), 0.5f, 0.5f);
}

// ---------------------------------------------------------------------------
// Kernel A: proj[v][perm(n)] = sum_k emb[v][k] * W_ih[n][k], perm(n) = unit*4+gate
// Block tile 128v x 128n, K=256 (R14 tiling: warp 64m x 32n; 8 LDSM / 16 HMMA).
__global__ void __launch_bounds__(256, 1)
proj_kernel(const float* __restrict__ emb, const float* __restrict__ W_ih)
{
    extern __shared__ unsigned char psm[];
    __half* sA = (__half*)psm;                          // [128][PPITCH] emb tile
    __half* sB = (__half*)(psm + 128 * PPITCH * 2);     // [128][PPITCH] W_ih tile

    const int tid = threadIdx.x;
    const int n0  = blockIdx.x * 128;
    const int v0  = blockIdx.y * 128;

    for (int idx = tid; idx < 128 * 64; idx += 256) {       // float4 granules
        const int r = idx >> 6, c4 = idx & 63;
        float4 va = make_float4(0.f, 0.f, 0.f, 0.f);
        if (v0 + r < VV) va = __ldg((const float4*)(emb + (size_t)(v0 + r) * EE) + c4);
        __half2* da = (__half2*)(sA + r * PPITCH + c4 * 4);
        da[0] = __floats2half2_rn(va.x, va.y); da[1] = __floats2half2_rn(va.z, va.w);
        const float4 vb = __ldg((const float4*)(W_ih + (size_t)(n0 + r) * EE) + c4);
        __half2* db = (__half2*)(sB + r * PPITCH + c4 * 4);
        db[0] = __floats2half2_rn(vb.x, vb.y); db[1] = __floats2half2_rn(vb.z, vb.w);
    }
    __syncthreads();

    const int lane = tid & 31, w = tid >> 5;
    const int mw = w >> 2;                  // 0..1 -> m offset mw*64
    const int nw = w & 3;                   // 0..3 -> n offset nw*32

    uint32_t aBase[4], bBase[4];
    #pragma unroll
    for (int mf = 0; mf < 4; ++mf)
        aBase[mf] = smem_u32(sA) + (mw * 64 + mf * 16 + (lane & 15)) * (PPITCH * 2)
                  + ((lane >> 4) & 1) * 16;
    #pragma unroll
    for (int j = 0; j < 4; ++j)
        bBase[j] = smem_u32(sB) + (nw * 32 + j * 8 + (lane & 7)) * (PPITCH * 2)
                 + ((lane >> 3) & 1) * 16;

    float d[4][4][4];
    #pragma unroll
    for (int mf = 0; mf < 4; ++mf)
        #pragma unroll
        for (int j = 0; j < 4; ++j)
            d[mf][j][0] = d[mf][j][1] = d[mf][j][2] = d[mf][j][3] = 0.0f;

    #pragma unroll 2
    for (int ks = 0; ks < 16; ++ks) {
        uint32_t a[4][4];
        #pragma unroll
        for (int mf = 0; mf < 4; ++mf)
            ldsm_x4(a[mf][0], a[mf][1], a[mf][2], a[mf][3], aBase[mf] + ks * 32);
        #pragma unroll
        for (int j = 0; j < 4; ++j) {
            uint32_t b0, b1;
            ldsm_x2(b0, b1, bBase[j] + ks * 32);
            #pragma unroll
            for (int mf = 0; mf < 4; ++mf)
                mma16816(d[mf][j], a[mf][0], a[mf][1], a[mf][2], a[mf][3], b0, b1);
        }
    }

    // Store with unit-major permutation: n = gate*512 + unit -> col (unit<<2)|gate
    const int cb = n0 + nw * 32 + (lane & 3) * 2;
    #pragma unroll
    for (int mf = 0; mf < 4; ++mf) {
        const int vr = v0 + mw * 64 + mf * 16 + (lane >> 2);
        __half* P0 = g_proj + (size_t)vr * 2048;
        __half* P1 = g_proj + (size_t)(vr + 8) * 2048;
        #pragma unroll
        for (int j = 0; j < 4; ++j) {
            const int na = cb + j * 8, nb = na + 1;
            const int pa = ((na & 511) << 2) | (na >> 9);
            const int pb = ((nb & 511) << 2) | (nb >> 9);
            P0[pa] = __float2half_rn(d[mf][j][0]);
            P0[pb] = __float2half_rn(d[mf][j][1]);
            P1[pa] = __float2half_rn(d[mf][j][2]);
            P1[pb] = __float2half_rn(d[mf][j][3]);
        }
    }
}

// ---------------------------------------------------------------------------
// Kernel B: persistent fused LSTM. grid = 128 blocks (8 rowgroups x 16 gate
// slices), 256 threads, 1 CTA/SM, all co-resident. Full-K warps: each warp
// computes m16 x n16 x k512 with B in registers -> complete accumulators, no
// cross-warp smem reduction. ONE block barrier per step (sH double-buffered).
// sW rows are UNIT-MAJOR: local row r = unit_local*4 + gate.
__global__ void __launch_bounds__(256, 1)
lstm_kernel(const int* __restrict__ tokens,
            const float* __restrict__ b_ih, const float* __restrict__ W_hh,
            const float* __restrict__ b_hh,
            const float* __restrict__ h0,   const float* __restrict__ c0)
{
    extern __shared__ unsigned char smem[];
    __half* sW  = (__half*)smem;                 // [128][WPITCH] W_hh slice (persistent)
    __half* sH0 = (__half*)(smem + OFF_H0);      // [16][HPITCH] h buffer, parity 0
    __half* sH1 = (__half*)(smem + OFF_H1);      // [16][HPITCH] h buffer, parity 1

    const int tid  = threadIdx.x;
    const int rg   = blockIdx.x >> 4;
    const int ns   = blockIdx.x & 15;
    const int row0 = rg * ROWG;

    // ---- sent_len scan (int scratch in sH0 region, consumed before h0 staging)
    int* s_first = (int*)sH0;
    if (tid < ROWG) s_first[tid] = TT;
    __syncthreads();
    {
        const int r = tid >> 4, sgi = tid & 15;
        const int4* tp = (const int4*)(tokens + (row0 + r) * TT + sgi * 64);
        int firstz = TT;
        #pragma unroll 4
        for (int q = 0; q < 16 && firstz == TT; ++q) {
            const int4 v = __ldg(tp + q);
            if (v.x == 0)      firstz = sgi * 64 + q * 4;
            else if (v.y == 0) firstz = sgi * 64 + q * 4 + 1;
            else if (v.z == 0) firstz = sgi * 64 + q * 4 + 2;
            else if (v.w == 0) firstz = sgi * 64 + q * 4 + 3;
        }
        if (firstz < TT) atomicMin(&s_first[r], firstz);
    }
    __syncthreads();
    int sentLen[ROWG];
    int tmax = 1;
    #pragma unroll
    for (int r = 0; r < ROWG; ++r) {
        int sl = s_first[r] - 1;
        if (sl < 0) sl = TT - 1;                 // python negative-index wrap (defensive)
        sentLen[r] = sl;
        tmax = max(tmax, sl);
    }
    __syncthreads();                             // scratch consumed

    // ---- W_hh slice -> SMEM fp16, UNIT-MAJOR rows: r = unit_local*4 + gate
    for (int idx = tid; idx < 128 * HH; idx += 256) {
        const int r    = idx >> 9;
        const int k    = idx & 511;
        const int unit = r >> 2, gate = r & 3;
        const int gr   = (gate << 9) + (ns << 5) + unit;   // gate*512 + ns*32 + unit
        sW[r * WPITCH + k] = __float2half_rn(W_hh[gr * HH + k]);
    }

    const int lane = tid & 31, wid = tid >> 5;

    // ---- per-thread cells: row rowL, units col0 and col0+2 (all 4 gates each)
    const int rowL = (lane >> 2) + 8 * (lane & 1);
    const int grow = row0 + rowL;
    const int u0   = (lane & 3) >> 1;                 // j=0 unit within warp quad
    const int col0 = (ns << 5) + (wid << 2) + u0;     // global unit col, cell j=0
    const int col1 = col0 + 2;                        // cell j=1
    float bias0[4], bias1[4];
    #pragma unroll
    for (int g = 0; g < 4; ++g) {
        bias0[g] = b_ih[(g << 9) + col0] + b_hh[(g << 9) + col0];
        bias1[g] = b_ih[(g << 9) + col1] + b_hh[(g << 9) + col1];
    }
    float cc0 = c0[grow * HH + col0];
    float cc1 = c0[grow * HH + col1];
    const int slA = sentLen[rowL];

    // ---- MMA geometry: warp = full-K m16 x n16 (gate-rows wid*16..wid*16+15)
    const uint32_t aB0 = smem_u32(sH0) + (lane & 15) * (HPITCH * 2) + ((lane >> 4) & 1) * 16;
    const uint32_t aB1 = smem_u32(sH1) + (lane & 15) * (HPITCH * 2) + ((lane >> 4) & 1) * 16;
    uint32_t bBase[2];
    #pragma unroll
    for (int j = 0; j < 2; ++j)
        bBase[j] = smem_u32(sW) + (wid * 16 + j * 8 + (lane & 7)) * (WPITCH * 2)
                 + ((lane >> 3) & 1) * 16;

    const int gr_r = tid >> 4;            // consumer-loader row 0..15
    const int gr_c = tid & 15;            // consumer-loader chunk (= producer rank)

    __syncthreads();                      // weights ready

    // ---- preload W_hh B-fragments into registers (stationary): 2 x 32 x 2
    uint32_t wb[2][32][2];
    #pragma unroll
    for (int ks = 0; ks < 32; ++ks)
        #pragma unroll
        for (int j = 0; j < 2; ++j)
            ldsm_x2(wb[j][ks][0], wb[j][ks][1], bBase[j] + ks * 32);

    // ---- prologue: xg(0) gather (unit-major proj: 2 x LDG.64) + token(1)
    uint2 xg0, xg1;
    {
        const int tok0 = tokens[grow * TT + 0];
        const __half* p = g_proj + (size_t)tok0 * 2048;
        xg0 = __ldg((const uint2*)(p + col0 * 4));
        xg1 = __ldg((const uint2*)(p + col1 * 4));
    }
    int tokN = tokens[grow * TT + 1];

    const unsigned* myCtr = &g_ctrB[rg][gr_c][0];   // my producer's counter
    unsigned* relCtr = &g_ctrB[rg][ns][0];          // my own release counter

    for (int t = 0; t <= tmax; ++t) {
        // ---- P1: prefetch xg(t+1)
        uint2 xn0, xn1;
        const bool doX = (t < tmax);
        if (doX) {
            const __half* p = g_proj + (size_t)tokN * 2048;
            xn0 = __ldg((const uint2*)(p + col0 * 4));
            xn1 = __ldg((const uint2*)(p + col1 * 4));
        }
        const int tokN2 = tokens[grow * TT + min(t + 2, TT - 1)];

        // ---- P2: acquire h(t-1) per-producer, stage own 64B chunk into buf t&1
        __half* sHc = (t & 1) ? sH1 : sH0;
        if (t == 0) {
            const float4* src = (const float4*)(h0 + (row0 + gr_r) * HH + gr_c * 32);
            __half2* dst = (__half2*)(sHc + gr_r * HPITCH + gr_c * 32);
            #pragma unroll
            for (int q = 0; q < 8; ++q) {
                const float4 v = __ldg(src + q);
                dst[2 * q]     = __floats2half2_rn(v.x, v.y);
                dst[2 * q + 1] = __floats2half2_rn(v.z, v.w);
            }
        } else {
            const unsigned target = 8u * (unsigned)t;   // 8 warps of producer block
            while ((int)(ld_acquire(myCtr) - target) < 0) { }
            const uint4* src = (const uint4*)(&g_hbuf[(t - 1) & 1][row0 + gr_r][gr_c * 32]);
            uint4* dst = (uint4*)((unsigned char*)sHc + gr_r * (HPITCH * 2) + gr_c * 64);
            #pragma unroll
            for (int q = 0; q < 4; ++q) dst[q] = __ldcg(src + q);   // L2-coherent
        }
        __syncthreads();        // ONLY block barrier: sH(t) staged (also proves
                                // all warps' reads of buf t&1 from step t-2 done)

        // ---- P3: full-K GEMM: m16 x n16 x k512 per warp, B in regs
        float d0[4] = {0.f, 0.f, 0.f, 0.f};
        float d1[4] = {0.f, 0.f, 0.f, 0.f};
        const uint32_t aB = (t & 1) ? aB1 : aB0;
        #pragma unroll
        for (int ks = 0; ks < 32; ++ks) {
            uint32_t a0, a1, a2, a3;
            ldsm_x4(a0, a1, a2, a3, aB + ks * 32);
            mma16816(d0, a0, a1, a2, a3, wb[0][ks][0], wb[0][ks][1]);
            mma16816(d1, a0, a1, a2, a3, wb[1][ks][0], wb[1][ks][1]);
        }

        // ---- P4: lane-pair shuffle: even lanes own row lane>>2, odd own +8;
        //      gates 0,1 live in even lanes' d[0..1], gates 2,3 in odd's d[2..3]
        const float r00 = __shfl_xor_sync(0xffffffffu, d0[0], 1);
        const float r01 = __shfl_xor_sync(0xffffffffu, d0[1], 1);
        const float r02 = __shfl_xor_sync(0xffffffffu, d0[2], 1);
        const float r03 = __shfl_xor_sync(0xffffffffu, d0[3], 1);
        const float r10 = __shfl_xor_sync(0xffffffffu, d1[0], 1);
        const float r11 = __shfl_xor_sync(0xffffffffu, d1[1], 1);
        const float r12 = __shfl_xor_sync(0xffffffffu, d1[2], 1);
        const float r13 = __shfl_xor_sync(0xffffffffu, d1[3], 1);
        const bool ev = (lane & 1) == 0;
        // cell0 (unit col0): gates i,f,g,o
        const float a0i = ev ? d0[0] : r02;
        const float a0f = ev ? d0[1] : r03;
        const float a0g = ev ? r00 : d0[2];
        const float a0o = ev ? r01 : d0[3];
        // cell1 (unit col1)
        const float a1i = ev ? d1[0] : r12;
        const float a1f = ev ? d1[1] : r13;
        const float a1g = ev ? r10 : d1[2];
        const float a1o = ev ? r11 : d1[3];

        // ---- P5: activations + cell update + publish h
        {
            const float2 xa = __half22float2(*(const __half2*)&xg0.x);
            const float2 xb = __half22float2(*(const __half2*)&xg0.y);
            const float gi = a0i + xa.x + bias0[0];
            const float gf = a0f + xa.y + bias0[1];
            const float gc = a0g + xb.x + bias0[2];
            const float go = a0o + xb.y + bias0[3];
            cc0 = siga(gf) * cc0 + siga(gi) * tanha(gc);
            const float hv = siga(go) * tanha(cc0);
            g_hbuf[t & 1][grow][col0] = __float2half_rn(hv);
            if (t == slA) { g_lastH[grow][col0] = hv; g_lastC[grow][col0] = cc0; }
        }
        {
            const float2 xa = __half22float2(*(const __half2*)&xg1.x);
            const float2 xb = __half22float2(*(const __half2*)&xg1.y);
            const float gi = a1i + xa.x + bias1[0];
            const float gf = a1f + xa.y + bias1[1];
            const float gc = a1g + xb.x + bias1[2];
            const float go = a1o + xb.y + bias1[3];
            cc1 = siga(gf) * cc1 + siga(gi) * tanha(gc);
            const float hv = siga(go) * tanha(cc1);
            g_hbuf[t & 1][grow][col1] = __float2half_rn(hv);
            if (t == slA) { g_lastH[grow][col1] = hv; g_lastC[grow][col1] = cc1; }
        }

        // ---- P6: per-warp release (syncwarp orders all lanes' h stores first)
        __syncwarp();
        if (lane == 0) red_release_add1(relCtr);

        xg0 = xn0; xg1 = xn1; tokN = tokN2;
    }
}

// ---------------------------------------------------------------------------
// Kernel C: head. One block per row. Resets the per-block counters so every
// launch / graph replay starts from zero.
__global__ void __launch_bounds__(256)
head_kernel(const float* __restrict__ W_proj, const float* __restrict__ b_proj,
            const float* __restrict__ W_out,  const float* __restrict__ b_out,
            float* __restrict__ out)
{
    __shared__ __align__(16) float last[2 * HH];
    __shared__ float y[HH];
    __shared__ float red[16];
    const int row = blockIdx.x, tid = threadIdx.x;

    if (tid == 0) g_ctrB[row >> 4][row & 15][0] = 0;

    for (int i = tid; i < HH; i += 256) {
        last[i]      = g_lastH[row][i];
        last[HH + i] = g_lastC[row][i];
    }
    __syncthreads();

    for (int j = tid; j < HH; j += 256) {
        const float4* w  = (const float4*)(W_proj + j * (2 * HH));
        const float4* l4 = (const float4*)last;
        float s = b_proj[j];
        #pragma unroll 8
        for (int k = 0; k < (2 * HH) / 4; ++k) {
            const float4 a = __ldg(w + k);
            const float4 b = l4[k];
            s += a.x * b.x + a.y * b.y + a.z * b.z + a.w * b.w;
        }
        y[j] = s;
    }
    __syncthreads();

    float s0 = 0.0f, s1 = 0.0f;
    for (int j = tid; j < HH; j += 256) {
        s0 += y[j] * W_out[j];
        s1 += y[j] * W_out[HH + j];
    }
    #pragma unroll
    for (int o = 16; o; o >>= 1) {
        s0 += __shfl_down_sync(0xffffffffu, s0, o);
        s1 += __shfl_down_sync(0xffffffffu, s1, o);
    }
    if ((tid & 31) == 0) { red[tid >> 5] = s0; red[8 + (tid >> 5)] = s1; }
    __syncthreads();
    if (tid == 0) {
        float a = b_out[0], b = b_out[1];
        #pragma unroll
        for (int w = 0; w < 8; ++w) { a += red[w]; b += red[8 + w]; }
        out[row * 2 + 0] = a;
        out[row * 2 + 1] = b;
    }
}

// ---------------------------------------------------------------------------
extern "C" void kernel_launch(void* const* d_in, const int* in_sizes, int n_in,
                              void* d_out, int out_size)
{
    (void)in_sizes; (void)n_in; (void)out_size;
    const int*   tokens = (const int*)  d_in[0];
    const float* emb    = (const float*)d_in[1];
    const float* W_ih   = (const float*)d_in[2];
    const float* b_ih   = (const float*)d_in[3];
    const float* W_hh   = (const float*)d_in[4];
    const float* b_hh   = (const float*)d_in[5];
    const float* W_proj = (const float*)d_in[6];
    const float* b_proj = (const float*)d_in[7];
    const float* W_out  = (const float*)d_in[8];
    const float* b_out  = (const float*)d_in[9];
    const float* h0     = (const float*)d_in[10];
    const float* c0     = (const float*)d_in[11];
    float* out = (float*)d_out;

    cudaFuncSetAttribute(proj_kernel, cudaFuncAttributeMaxDynamicSharedMemorySize, PSMEM);
    cudaFuncSetAttribute(lstm_kernel, cudaFuncAttributeMaxDynamicSharedMemorySize, SMEM_BYTES);

    proj_kernel<<<dim3(16, 393), 256, PSMEM>>>(emb, W_ih);
    lstm_kernel<<<NRG * NSPL, 256, SMEM_BYTES>>>(tokens, b_ih, W_hh, b_hh, h0, c0);
    head_kernel<<<BB, 256>>>(W_proj, b_proj, W_out, b_out, out);
}

// round 17
// speedup vs baseline: 1.1748x; 1.1748x over previous
#include <cuda_runtime.h>
#include <cuda_fp16.h>
#include <stdint.h>

// Problem constants
#define VV   50257
#define VPAD 50304          // 393 * 128
#define BB   128
#define TT   1024
#define EE   256
#define HH   512
#define ROWG 16             // rows per rowgroup
#define NRG  8              // rowgroups
#define NSPL 16             // gate-split blocks per rowgroup
#define WPITCH 520          // W_hh smem pitch (halfs): 1040B, %128=16 -> conflict-free ldmatrix
#define HPITCH 520          // h buffer pitch (halfs)
#define GP     130          // gate slab pitch (floats)
#define OFF_H  (128 * WPITCH * 2)               // 133120
#define OFF_G  (OFF_H + ROWG * HPITCH * 2)      // 149760
#define SMEM_BYTES (OFF_G + 2 * ROWG * GP * 4)  // 166400 <= 232448 cap

#define PPITCH 264          // proj kernel smem pitch (halfs): 528B, %128=16
#define PSMEM  (2 * 128 * PPITCH * 2)           // 135168 B -> 1 CTA/SM

// Persistent device scratch
// g_proj layout is GATE-MAJOR: proj[v][gate*512 + unit]
__device__ __half   g_proj[(size_t)VPAD * 2048];  // 206 MB
__device__ __half   g_hbuf[2][BB][HH];            // double-buffered recurrent h (fp16)
__device__ float    g_lastH[BB][HH];
__device__ float    g_lastC[BB][HH];
__device__ unsigned g_ctrB[NRG][NSPL][32];        // per-producer-block counters, 128B apart

// ---------------------------------------------------------------------------
__device__ __forceinline__ uint32_t smem_u32(const void* p) {
    return (uint32_t)__cvta_generic_to_shared(p);
}
__device__ __forceinline__ void ldsm_x4(uint32_t& r0, uint32_t& r1, uint32_t& r2, uint32_t& r3, uint32_t a) {
    asm volatile("ldmatrix.sync.aligned.m8n8.x4.shared.b16 {%0,%1,%2,%3}, [%4];\n"
                 : "=r"(r0), "=r"(r1), "=r"(r2), "=r"(r3) : "r"(a));
}
__device__ __forceinline__ void ldsm_x2(uint32_t& r0, uint32_t& r1, uint32_t a) {
    asm volatile("ldmatrix.sync.aligned.m8n8.x2.shared.b16 {%0,%1}, [%2];\n"
                 : "=r"(r0), "=r"(r1) : "r"(a));
}
__device__ __forceinline__ void mma16816(float* d, uint32_t a0, uint32_t a1, uint32_t a2, uint32_t a3,
                                         uint32_t b0, uint32_t b1) {
    asm volatile("mma.sync.aligned.m16n8k16.row.col.f32.f16.f16.f32 "
                 "{%0,%1,%2,%3}, {%4,%5,%6,%7}, {%8,%9}, {%0,%1,%2,%3};\n"
                 : "+f"(d[0]), "+f"(d[1]), "+f"(d[2]), "+f"(d[3])
                 : "r"(a0), "r"(a1), "r"(a2), "r"(a3), "r"(b0), "r"(b1));
}
__device__ __forceinline__ unsigned ld_acquire(const unsigned* p) {
    unsigned v;
    asm volatile("ld.global.acquire.gpu.b32 %0, [%1];\n" : "=r"(v) : "l"(p) : "memory");
    return v;
}
__device__ __forceinline__ void red_release_add1(unsigned* p) {
    asm volatile("red.release.gpu.global.add.u32 [%0], %1;\n" :: "l"(p), "r"(1u) : "memory");
}
// MUFU.TANH-based activations: 1 MUFU each
__device__ __forceinline__ float tanha(float x) {
    float y; asm("tanh.approx.f32 %0, %1;\n" : "=f"(y) : "f"(x)); return y;
}
__device__ __forceinline__ float siga(float x) {
    return fmaf(tanha(0.5f * x), 0.5f, 0.5f);
}

// ---------------------------------------------------------------------------
// Kernel A: proj[v][n] = sum_k emb[v][k] * W_ih[n][k]   (fp16 out, fp32 accum)
// Block tile 128v x 128n, K=256. Warp tile 64m x 32n (8 warps = 2m x 4n):
// 8 LDSM per 16 HMMA. Gate-major output (coalesced half2 stores).
__global__ void __launch_bounds__(256, 1)
proj_kernel(const float* __restrict__ emb, const float* __restrict__ W_ih)
{
    extern __shared__ unsigned char psm[];
    __half* sA = (__half*)psm;                          // [128][PPITCH] emb tile
    __half* sB = (__half*)(psm + 128 * PPITCH * 2);     // [128][PPITCH] W_ih tile

    const int tid = threadIdx.x;
    const int n0  = blockIdx.x * 128;
    const int v0  = blockIdx.y * 128;

    for (int idx = tid; idx < 128 * 64; idx += 256) {       // float4 granules
        const int r = idx >> 6, c4 = idx & 63;
        float4 va = make_float4(0.f, 0.f, 0.f, 0.f);
        if (v0 + r < VV) va = __ldg((const float4*)(emb + (size_t)(v0 + r) * EE) + c4);
        __half2* da = (__half2*)(sA + r * PPITCH + c4 * 4);
        da[0] = __floats2half2_rn(va.x, va.y); da[1] = __floats2half2_rn(va.z, va.w);
        const float4 vb = __ldg((const float4*)(W_ih + (size_t)(n0 + r) * EE) + c4);
        __half2* db = (__half2*)(sB + r * PPITCH + c4 * 4);
        db[0] = __floats2half2_rn(vb.x, vb.y); db[1] = __floats2half2_rn(vb.z, vb.w);
    }
    __syncthreads();

    const int lane = tid & 31, w = tid >> 5;
    const int mw = w >> 2;                  // 0..1 -> m offset mw*64
    const int nw = w & 3;                   // 0..3 -> n offset nw*32

    uint32_t aBase[4], bBase[4];
    #pragma unroll
    for (int mf = 0; mf < 4; ++mf)
        aBase[mf] = smem_u32(sA) + (mw * 64 + mf * 16 + (lane & 15)) * (PPITCH * 2)
                  + ((lane >> 4) & 1) * 16;
    #pragma unroll
    for (int j = 0; j < 4; ++j)
        bBase[j] = smem_u32(sB) + (nw * 32 + j * 8 + (lane & 7)) * (PPITCH * 2)
                 + ((lane >> 3) & 1) * 16;

    float d[4][4][4];
    #pragma unroll
    for (int mf = 0; mf < 4; ++mf)
        #pragma unroll
        for (int j = 0; j < 4; ++j)
            d[mf][j][0] = d[mf][j][1] = d[mf][j][2] = d[mf][j][3] = 0.0f;

    #pragma unroll 2
    for (int ks = 0; ks < 16; ++ks) {
        uint32_t a[4][4];
        #pragma unroll
        for (int mf = 0; mf < 4; ++mf)
            ldsm_x4(a[mf][0], a[mf][1], a[mf][2], a[mf][3], aBase[mf] + ks * 32);
        #pragma unroll
        for (int j = 0; j < 4; ++j) {
            uint32_t b0, b1;
            ldsm_x2(b0, b1, bBase[j] + ks * 32);
            #pragma unroll
            for (int mf = 0; mf < 4; ++mf)
                mma16816(d[mf][j], a[mf][0], a[mf][1], a[mf][2], a[mf][3], b0, b1);
        }
    }

    // Store: rows v0 + mw*64 + mf*16 + (lane>>2) (+8), cols n0 + nw*32 + j*8 + (lane&3)*2
    const int cb = n0 + nw * 32 + (lane & 3) * 2;
    #pragma unroll
    for (int mf = 0; mf < 4; ++mf) {
        const int vr = v0 + mw * 64 + mf * 16 + (lane >> 2);
        __half* P0 = g_proj + (size_t)vr * 2048 + cb;
        __half* P1 = g_proj + (size_t)(vr + 8) * 2048 + cb;
        #pragma unroll
        for (int j = 0; j < 4; ++j) {
            *(__half2*)(P0 + j * 8) = __floats2half2_rn(d[mf][j][0], d[mf][j][1]);
            *(__half2*)(P1 + j * 8) = __floats2half2_rn(d[mf][j][2], d[mf][j][3]);
        }
    }
}

// ---------------------------------------------------------------------------
// Kernel B: persistent fused LSTM recurrence (R15 design). grid = 128 blocks
// (8 rowgroups x 16 gate-slices), 256 threads, 1 CTA/SM, all co-resident.
// Warp = (k-half of 256, n-tile of 32 gate cols); B-frags in registers; fp32
// slab reduction across the two k-halves; per-producer-block counters with
// release-atomics (consumer thread (gr_r, gr_c) polls only block gr_c).
__global__ void __launch_bounds__(256, 1)
lstm_kernel(const int* __restrict__ tokens,
            const float* __restrict__ b_ih, const float* __restrict__ W_hh,
            const float* __restrict__ b_hh,
            const float* __restrict__ h0,   const float* __restrict__ c0)
{
    extern __shared__ unsigned char smem[];
    __half* sW = (__half*)smem;                 // [128][WPITCH] W_hh slice (persistent)
    __half* sH = (__half*)(smem + OFF_H);       // [16][HPITCH] h buffer
    float*  sG = (float*)(smem + OFF_G);        // 2 slabs [16][GP] gate partials

    const int tid  = threadIdx.x;
    const int rg   = blockIdx.x >> 4;
    const int ns   = blockIdx.x & 15;
    const int row0 = rg * ROWG;

    // ---- sent_len scan (int scratch in sG region, consumed before gate use)
    int* s_first = (int*)sG;
    if (tid < ROWG) s_first[tid] = TT;
    __syncthreads();
    {
        const int r = tid >> 4, sgi = tid & 15;
        const int4* tp = (const int4*)(tokens + (row0 + r) * TT + sgi * 64);
        int firstz = TT;
        #pragma unroll 4
        for (int q = 0; q < 16 && firstz == TT; ++q) {
            const int4 v = __ldg(tp + q);
            if (v.x == 0)      firstz = sgi * 64 + q * 4;
            else if (v.y == 0) firstz = sgi * 64 + q * 4 + 1;
            else if (v.z == 0) firstz = sgi * 64 + q * 4 + 2;
            else if (v.w == 0) firstz = sgi * 64 + q * 4 + 3;
        }
        if (firstz < TT) atomicMin(&s_first[r], firstz);
    }
    __syncthreads();
    int sentLen[ROWG];
    int tmax = 1;
    #pragma unroll
    for (int r = 0; r < ROWG; ++r) {
        int sl = s_first[r] - 1;
        if (sl < 0) sl = TT - 1;                 // python negative-index wrap (defensive)
        sentLen[r] = sl;
        tmax = max(tmax, sl);
    }
    __syncthreads();                             // scratch consumed

    // ---- W_hh slice -> SMEM fp16: local gate row r -> gr = gate*512 + ns*32 + unit
    for (int idx = tid; idx < 128 * HH; idx += 256) {
        const int r  = idx >> 9;
        const int k  = idx & 511;
        const int gr = ((r >> 5) << 9) + (ns << 5) + (r & 31);
        sW[r * WPITCH + k] = __float2half_rn(W_hh[gr * HH + k]);
    }

    // ---- per-thread cell state: same row, adjacent units
    const int rA = tid >> 4;
    const int uA = (tid & 15) * 2, uB = uA + 1;
    const int colA = (ns << 5) + uA, colB = colA + 1;
    const int growA = row0 + rA;
    const float biA = b_ih[colA]        + b_hh[colA];
    const float bfA = b_ih[512 + colA]  + b_hh[512 + colA];
    const float bgA = b_ih[1024 + colA] + b_hh[1024 + colA];
    const float boA = b_ih[1536 + colA] + b_hh[1536 + colA];
    const float biB = b_ih[colB]        + b_hh[colB];
    const float bfB = b_ih[512 + colB]  + b_hh[512 + colB];
    const float bgB = b_ih[1024 + colB] + b_hh[1024 + colB];
    const float boB = b_ih[1536 + colB] + b_hh[1536 + colB];
    float cA = c0[growA * HH + colA];
    float cB = c0[growA * HH + colB];
    const int slA = sentLen[rA];

    // ---- warp MMA geometry: warp = (k-half of 256, n-tile of 32 gate cols)
    const int lane = tid & 31, wid = tid >> 5;
    const int kh = wid >> 2;
    const int nt = wid & 3;

    const int a_row = lane & 15;
    const int asel  = ((lane >> 4) & 1) * 16;
    const uint32_t aH = smem_u32(sH) + a_row * (HPITCH * 2) + asel + kh * 512;

    uint32_t bH[4];
    const int b_lrow = lane & 7;
    const int b_csel = ((lane >> 3) & 1) * 16;
    #pragma unroll
    for (int j = 0; j < 4; ++j)
        bH[j] = smem_u32(sW) + (nt * 32 + j * 8 + b_lrow) * (WPITCH * 2) + b_csel + kh * 512;

    const int gr_r = tid >> 4;            // loader row 0..15
    const int gr_c = tid & 15;            // loader chunk 0..15 (= producer block rank)

    __syncthreads();                      // weights ready

    // ---- preload W_hh B-fragments into registers (stationary)
    uint32_t wb[4][16][2];
    #pragma unroll
    for (int ks = 0; ks < 16; ++ks)
        #pragma unroll
        for (int j = 0; j < 4; ++j)
            ldsm_x2(wb[j][ks][0], wb[j][ks][1], bH[j] + ks * 32);

    // ---- prologue: xg(0) gather + token(1)
    uint32_t xgCur[4];
    {
        const int tok0 = tokens[growA * TT + 0];
        const __half* p = g_proj + (size_t)tok0 * 2048 + colA;
        #pragma unroll
        for (int g = 0; g < 4; ++g) xgCur[g] = __ldg((const uint32_t*)(p + g * 512));
    }
    int tokN = tokens[growA * TT + 1];

    const unsigned* myCtr = &g_ctrB[rg][gr_c][0];   // my producer's counter
    unsigned* relCtr = &g_ctrB[rg][ns][0];          // my own release counter

    for (int t = 0; t <= tmax; ++t) {
        // ---- P1: prefetch xg(t+1) gather into registers (full-step cover)
        uint32_t xgn[4];
        const bool doX = (t < tmax);
        if (doX) {
            const __half* p = g_proj + (size_t)tokN * 2048 + colA;
            #pragma unroll
            for (int g = 0; g < 4; ++g) xgn[g] = __ldg((const uint32_t*)(p + g * 512));
        }
        const int tokN2 = tokens[growA * TT + min(t + 2, TT - 1)];

        // ---- P2: acquire h(t-1) per-producer, then load own 64B chunk
        if (t == 0) {
            const float4* src = (const float4*)(h0 + (row0 + gr_r) * HH + gr_c * 32);
            __half2* dst = (__half2*)(sH + gr_r * HPITCH + gr_c * 32);
            #pragma unroll
            for (int q = 0; q < 8; ++q) {
                const float4 v = __ldg(src + q);
                dst[2 * q]     = __floats2half2_rn(v.x, v.y);
                dst[2 * q + 1] = __floats2half2_rn(v.z, v.w);
            }
        } else {
            const unsigned target = 8u * (unsigned)t;   // 8 warps of producer block
            while ((int)(ld_acquire(myCtr) - target) < 0) { }
            const uint4* src = (const uint4*)(&g_hbuf[(t - 1) & 1][row0 + gr_r][gr_c * 32]);
            uint4* dst = (uint4*)((unsigned char*)sH + gr_r * (HPITCH * 2) + gr_c * 64);
            #pragma unroll
            for (int q = 0; q < 4; ++q) dst[q] = __ldcg(src + q);   // L2-coherent
        }
        __syncthreads();                       // sync1: sH fully assembled

        // ---- P3: h-GEMM (critical path): m16 x n32 x k256 per warp, B in regs
        float d[4][4];
        #pragma unroll
        for (int j = 0; j < 4; ++j) d[j][0] = d[j][1] = d[j][2] = d[j][3] = 0.0f;
        #pragma unroll
        for (int ks = 0; ks < 16; ++ks) {
            uint32_t a0, a1, a2, a3;
            ldsm_x4(a0, a1, a2, a3, aH + ks * 32);
            #pragma unroll
            for (int j = 0; j < 4; ++j)
                mma16816(d[j], a0, a1, a2, a3, wb[j][ks][0], wb[j][ks][1]);
        }

        // ---- P4: gate partials -> slab kh
        {
            const int gg = lane >> 2, tg = lane & 3;
            float* base = sG + (kh * 16 + gg) * GP + nt * 32 + tg * 2;
            #pragma unroll
            for (int j = 0; j < 4; ++j) {
                float* p = base + j * 8;
                *(float2*)p            = make_float2(d[j][0], d[j][1]);
                *(float2*)(p + 8 * GP) = make_float2(d[j][2], d[j][3]);
            }
        }
        __syncthreads();                       // sync2: slabs complete (+ sH reads done)

        // ---- P5: activations + cell update, vectorized slab reads, MUFU.TANH
        {
            const float2* q0 = (const float2*)(sG + rA * GP);
            const float2* q1 = (const float2*)(sG + (16 + rA) * GP);
            const int u2 = uA >> 1;
            const float2 pi = q0[u2],      ri = q1[u2];
            const float2 pf = q0[16 + u2], rf = q1[16 + u2];
            const float2 pg = q0[32 + u2], rg2 = q1[32 + u2];
            const float2 po = q0[48 + u2], ro = q1[48 + u2];
            const float2 xi = __half22float2(*(__half2*)&xgCur[0]);
            const float2 xf = __half22float2(*(__half2*)&xgCur[1]);
            const float2 xg = __half22float2(*(__half2*)&xgCur[2]);
            const float2 xo = __half22float2(*(__half2*)&xgCur[3]);
            float hvA, hvB;
            {
                const float gi = pi.x + ri.x + xi.x + biA;
                const float gf = pf.x + rf.x + xf.x + bfA;
                const float gc = pg.x + rg2.x + xg.x + bgA;
                const float go = po.x + ro.x + xo.x + boA;
                cA = siga(gf) * cA + siga(gi) * tanha(gc);
                hvA = siga(go) * tanha(cA);
            }
            {
                const float gi = pi.y + ri.y + xi.y + biB;
                const float gf = pf.y + rf.y + xf.y + bfB;
                const float gc = pg.y + rg2.y + xg.y + bgB;
                const float go = po.y + ro.y + xo.y + boB;
                cB = siga(gf) * cB + siga(gi) * tanha(gc);
                hvB = siga(go) * tanha(cB);
            }
            *(__half2*)&g_hbuf[t & 1][growA][colA] =
                __halves2half2(__float2half_rn(hvA), __float2half_rn(hvB));
            if (t == slA) {
                g_lastH[growA][colA] = hvA; g_lastC[growA][colA] = cA;
                g_lastH[growA][colB] = hvB; g_lastC[growA][colB] = cB;
            }
        }

        // ---- P6: per-warp release. __syncwarp orders all lanes' h stores
        //      before lane0's release-atomic (cumulativity); no membar needed.
        __syncwarp();
        if (lane == 0) red_release_add1(relCtr);

        #pragma unroll
        for (int g = 0; g < 4; ++g) xgCur[g] = xgn[g];
        tokN = tokN2;
    }
}

// ---------------------------------------------------------------------------
// Kernel C: head. One block per row. Resets the per-block counters so every
// launch / graph replay starts from zero.
__global__ void __launch_bounds__(256)
head_kernel(const float* __restrict__ W_proj, const float* __restrict__ b_proj,
            const float* __restrict__ W_out,  const float* __restrict__ b_out,
            float* __restrict__ out)
{
    __shared__ __align__(16) float last[2 * HH];
    __shared__ float y[HH];
    __shared__ float red[16];
    const int row = blockIdx.x, tid = threadIdx.x;

    if (tid == 0) g_ctrB[row >> 4][row & 15][0] = 0;

    for (int i = tid; i < HH; i += 256) {
        last[i]      = g_lastH[row][i];
        last[HH + i] = g_lastC[row][i];
    }
    __syncthreads();

    for (int j = tid; j < HH; j += 256) {
        const float4* w  = (const float4*)(W_proj + j * (2 * HH));
        const float4* l4 = (const float4*)last;
        float s = b_proj[j];
        #pragma unroll 8
        for (int k = 0; k < (2 * HH) / 4; ++k) {
            const float4 a = __ldg(w + k);
            const float4 b = l4[k];
            s += a.x * b.x + a.y * b.y + a.z * b.z + a.w * b.w;
        }
        y[j] = s;
    }
    __syncthreads();

    float s0 = 0.0f, s1 = 0.0f;
    for (int j = tid; j < HH; j += 256) {
        s0 += y[j] * W_out[j];
        s1 += y[j] * W_out[HH + j];
    }
    #pragma unroll
    for (int o = 16; o; o >>= 1) {
        s0 += __shfl_down_sync(0xffffffffu, s0, o);
        s1 += __shfl_down_sync(0xffffffffu, s1, o);
    }
    if ((tid & 31) == 0) { red[tid >> 5] = s0; red[8 + (tid >> 5)] = s1; }
    __syncthreads();
    if (tid == 0) {
        float a = b_out[0], b = b_out[1];
        #pragma unroll
        for (int w = 0; w < 8; ++w) { a += red[w]; b += red[8 + w]; }
        out[row * 2 + 0] = a;
        out[row * 2 + 1] = b;
    }
}

// ---------------------------------------------------------------------------
extern "C" void kernel_launch(void* const* d_in, const int* in_sizes, int n_in,
                              void* d_out, int out_size)
{
    (void)in_sizes; (void)n_in; (void)out_size;
    const int*   tokens = (const int*)  d_in[0];
    const float* emb    = (const float*)d_in[1];
    const float* W_ih   = (const float*)d_in[2];
    const float* b_ih   = (const float*)d_in[3];
    const float* W_hh   = (const float*)d_in[4];
    const float* b_hh   = (const float*)d_in[5];
    const float* W_proj = (const float*)d_in[6];
    const float* b_proj = (const float*)d_in[7];
    const float* W_out  = (const float*)d_in[8];
    const float* b_out  = (const float*)d_in[9];
    const float* h0     = (const float*)d_in[10];
    const float* c0     = (const float*)d_in[11];
    float* out = (float*)d_out;

    cudaFuncSetAttribute(proj_kernel, cudaFuncAttributeMaxDynamicSharedMemorySize, PSMEM);
    cudaFuncSetAttribute(lstm_kernel, cudaFuncAttributeMaxDynamicSharedMemorySize, SMEM_BYTES);

    proj_kernel<<<dim3(16, 393), 256, PSMEM>>>(emb, W_ih);
    lstm_kernel<<<NRG * NSPL, 256, SMEM_BYTES>>>(tokens, b_ih, W_hh, b_hh, h0, c0);
    head_kernel<<<BB, 256>>>(W_proj, b_proj, W_out, b_out, out);
}